// round 8
// baseline (speedup 1.0000x reference)
#include <cuda_runtime.h>
#include <cuda_bf16.h>
#include <math.h>
#include <stdint.h>

// Problem dims
#define BB 64
#define CC 256
#define HWN 1024
#define SS 512
#define DD 256
#define TAUV 0.07f
#define SIGMA (1.0f/1024.0f)

// ---------------- scratch (static device globals; no allocation) ----------------
__device__ float g_patches[(size_t)BB*HWN*DD];   // 64 MB  [b][p][d]
__device__ float g_tokens [(size_t)BB*SS*DD];    // 32 MB  [b][s][d]
__device__ float g_sim    [(size_t)BB*HWN*SS];   // 128 MB [b][p][s]
__device__ float g_lgve   [(size_t)BB*SS*DD];    // 32 MB
__device__ float g_fsim   [(size_t)BB*SS*SS];    // 64 MB  [b][i][j]
__device__ float    g_psumV[BB*DD];   // column sums of patches (mean-pool)
__device__ float    g_psumT[BB*DD];
__device__ float    g_nv2[BB*SS];     // lgve row sumsq
__device__ float    g_nt2[BB*SS];     // tokens row sumsq
__device__ uint32_t g_mnU[BB*SS];     // sim column min (encoded)
__device__ uint32_t g_mxU[BB*SS];     // sim column max (encoded)
__device__ float g_gimg[BB*DD];
__device__ float g_gtxt[BB*DD];
__device__ float g_norms[128];
__device__ float g_gsim[64*64];
__device__ float g_rowterm[BB*SS];
__device__ float g_colterm[BB*SS];
__device__ float g_gloss;

// ---------------- helpers ----------------
__device__ __forceinline__ uint32_t encf(float f) {
    uint32_t u = __float_as_uint(f);
    return ((int)u < 0) ? ~u : (u | 0x80000000u);
}
__device__ __forceinline__ float decf(uint32_t u) {
    return ((int)u < 0) ? __uint_as_float(u & 0x7fffffffu) : __uint_as_float(~u);
}

// bf16 hi/lo split of a pair -> packed bf16x2 words (x0 in low half)
__device__ __forceinline__ void split_pair(float x0, float x1, uint32_t& h, uint32_t& l) {
    asm("cvt.rn.bf16x2.f32 %0, %1, %2;" : "=r"(h) : "f"(x1), "f"(x0));
    float f0 = __uint_as_float(h << 16);           // bf16(x0)
    float f1 = __uint_as_float(h & 0xffff0000u);   // bf16(x1)
    asm("cvt.rn.bf16x2.f32 %0, %1, %2;" : "=r"(l) : "f"(x1 - f1), "f"(x0 - f0));
}

__device__ __forceinline__ void mma16816(float* c, const uint32_t* a, const uint32_t* b2) {
    asm volatile(
        "mma.sync.aligned.m16n8k16.row.col.f32.bf16.bf16.f32 "
        "{%0,%1,%2,%3},{%4,%5,%6,%7},{%8,%9},{%0,%1,%2,%3};"
        : "+f"(c[0]), "+f"(c[1]), "+f"(c[2]), "+f"(c[3])
        : "r"(a[0]), "r"(a[1]), "r"(a[2]), "r"(a[3]), "r"(b2[0]), "r"(b2[1]));
}

// SMEM layout (dynamic):
//   [0,512)        bias (128 floats)
//   [512,1536)     red: 256 floats (ZDIV zpart) / 2x128 uints (MINMAX)
//   [1536,2048)    aux: 128 floats (ZDIV zinv / COLSUM scol)
//   [2048,2560)    srow: 128 floats (ROWSS)
//   [2560, +64K)   A/B double buffers
#define OFF_RED  512
#define OFF_AUX  1536
#define OFF_ROW  2048
#define OFF_AB   2560
#define TILEB    16384
#define SMEMSZ   (2560 + 4*16384)

// EX bits: 1=COLSUM (atomicAdd column sums), 2=ROWSS (row sumsq), 4=MINMAX (sim col stats), 8=ZDIV (lgve)
// AMODE: 0 = A[m][k] row-major; 1 = A[k][m] (m contiguous); 2 = mode1 + lgve weight xform
// BMODE: 0 = B[n][k] row-major; 1 = B[k][n] (n contiguous)
// EP:    0 plain; 1 +bias[n]; 2 *scale
// NRM:   1 = L2-normalize A rows by g_nv2, B rows by g_nt2 during staging (fsim)
template<int AMODE, int BMODE, int EP, int EX, int NRM>
__device__ __forceinline__ void tc_gemm(
    const float* __restrict__ A, const float* __restrict__ B, float* __restrict__ C,
    int K, int lda, int ldb, int ldc, size_t sA, size_t sB, size_t sC,
    const float* __restrict__ bias, float scale,
    float* __restrict__ colsum, float* __restrict__ rowss)
{
    extern __shared__ char smem[];
    float* sbias = (float*)smem;
    float* red   = (float*)(smem + OFF_RED);
    float* aux   = (float*)(smem + OFF_AUX);
    float* srow  = (float*)(smem + OFF_ROW);
    uint32_t* smnU = (uint32_t*)(smem + OFF_RED);
    uint32_t* smxU = (uint32_t*)(smem + OFF_RED + 512);
    float* scol  = (float*)(smem + OFF_AUX);
    char* bufA0 = smem + OFF_AB;
    char* bufB0 = smem + OFF_AB + 2*TILEB;

    int tid = threadIdx.x, lane = tid & 31, wid = tid >> 5;
    int g = lane >> 2, tg = lane & 3;
    int wm = wid & 1, wn = wid >> 1;       // 2 x 4 warp grid; warp tile 64x32
    int b = blockIdx.z;
    int m0 = blockIdx.x * 128, n0 = blockIdx.y * 128;

    const float* Abase = (AMODE == 0) ? (A + (size_t)b*sA + (size_t)m0*lda)
                                      : (A + (size_t)b*sA + m0);
    const float* Bbase = (BMODE == 0) ? (B + (size_t)b*sB + (size_t)n0*ldb)
                                      : (B + (size_t)b*sB + n0);
    float* Cb = C + (size_t)b*sC;

    if (EP == 1 && tid < 128) sbias[tid] = bias[n0 + tid];
    if ((EX & 1) && tid < 128) scol[tid] = 0.f;
    if ((EX & 2) && tid < 128) srow[tid] = 0.f;
    if ((EX & 4) && tid < 128) { smnU[tid] = 0xFFFFFFFFu; smxU[tid] = 0u; }

    // staging maps
    const int aRow = (AMODE == 0) ? (tid >> 1) : (tid & 127);
    const int aSeg = (AMODE == 0) ? ((tid & 1) * 16) : ((tid >> 7) * 16);
    const int bRow = (BMODE == 0) ? (tid >> 1) : (tid & 127);
    const int bSeg = (BMODE == 0) ? ((tid & 1) * 16) : ((tid >> 7) * 16);

    float xmn = 0.f, xri = 0.f, zp = 0.f;
    if (AMODE == 2) {
        float mn = decf(g_mnU[b*SS + m0 + aRow]);
        float mx = decf(g_mxU[b*SS + m0 + aRow]);
        xmn = mn; xri = 1.0f / (mx - mn + 1e-8f);
    }
    float invA = 1.f, invB = 1.f;
    if (NRM) {
        invA = 1.0f / fmaxf(sqrtf(g_nv2[b*SS + m0 + aRow]), 1e-8f);
        invB = 1.0f / fmaxf(sqrtf(g_nt2[b*SS + n0 + bRow]), 1e-8f);
    }

    float acc[4][4][4];
#pragma unroll
    for (int i = 0; i < 4; i++)
#pragma unroll
        for (int j = 0; j < 4; j++)
#pragma unroll
            for (int q = 0; q < 4; q++) acc[i][j][q] = 0.f;

    auto ldgA = [&](int c, float* v) {
        if (AMODE == 0) {
            const float* p = Abase + (size_t)aRow * lda + c*32 + aSeg;
            *(float4*)(v+0)  = *(const float4*)(p+0);
            *(float4*)(v+4)  = *(const float4*)(p+4);
            *(float4*)(v+8)  = *(const float4*)(p+8);
            *(float4*)(v+12) = *(const float4*)(p+12);
        } else {
            const float* p = Abase + (size_t)(c*32 + aSeg) * lda + aRow;
#pragma unroll
            for (int q = 0; q < 16; q++) v[q] = p[(size_t)q * lda];
        }
    };
    auto ldgB = [&](int c, float* v) {
        if (BMODE == 0) {
            const float* p = Bbase + (size_t)bRow * ldb + c*32 + bSeg;
            *(float4*)(v+0)  = *(const float4*)(p+0);
            *(float4*)(v+4)  = *(const float4*)(p+4);
            *(float4*)(v+8)  = *(const float4*)(p+8);
            *(float4*)(v+12) = *(const float4*)(p+12);
        } else {
            const float* p = Bbase + (size_t)(c*32 + bSeg) * ldb + bRow;
#pragma unroll
            for (int q = 0; q < 16; q++) v[q] = p[(size_t)q * ldb];
        }
    };
    auto stsA = [&](int buf, float* v) {
        if (AMODE == 2) {
#pragma unroll
            for (int q = 0; q < 16; q++) {
                float t = (v[q] - xmn) * xri;
                t = (t < SIGMA) ? 0.f : t;
                zp += t;
                v[q] = t;
            }
        }
        if (NRM) {
#pragma unroll
            for (int q = 0; q < 16; q++) v[q] *= invA;
        }
        uint32_t h[8], l[8];
#pragma unroll
        for (int q = 0; q < 8; q++) split_pair(v[2*q], v[2*q+1], h[q], l[q]);
        char* dst = bufA0 + buf*TILEB + aRow*128;
        int mask = (aRow & 7) << 4, cb = aSeg * 2;
        *(uint4*)(dst + ((cb     ) ^ mask)) = make_uint4(h[0], h[1], h[2], h[3]);
        *(uint4*)(dst + ((cb + 16) ^ mask)) = make_uint4(h[4], h[5], h[6], h[7]);
        *(uint4*)(dst + ((cb + 64) ^ mask)) = make_uint4(l[0], l[1], l[2], l[3]);
        *(uint4*)(dst + ((cb + 80) ^ mask)) = make_uint4(l[4], l[5], l[6], l[7]);
    };
    auto stsB = [&](int buf, float* v) {
        if (NRM) {
#pragma unroll
            for (int q = 0; q < 16; q++) v[q] *= invB;
        }
        uint32_t h[8], l[8];
#pragma unroll
        for (int q = 0; q < 8; q++) split_pair(v[2*q], v[2*q+1], h[q], l[q]);
        char* dst = bufB0 + buf*TILEB + bRow*128;
        int mask = (bRow & 7) << 4, cb = bSeg * 2;
        *(uint4*)(dst + ((cb     ) ^ mask)) = make_uint4(h[0], h[1], h[2], h[3]);
        *(uint4*)(dst + ((cb + 16) ^ mask)) = make_uint4(h[4], h[5], h[6], h[7]);
        *(uint4*)(dst + ((cb + 64) ^ mask)) = make_uint4(l[0], l[1], l[2], l[3]);
        *(uint4*)(dst + ((cb + 80) ^ mask)) = make_uint4(l[4], l[5], l[6], l[7]);
    };

    float va[16], vb[16];
    ldgA(0, va); ldgB(0, vb);
    stsA(0, va); stsB(0, vb);
    __syncthreads();

    const int nch = K / 32;
    const int mask = g << 4;
    for (int c = 0; c < nch; c++) {
        if (c + 1 < nch) { ldgA(c + 1, va); ldgB(c + 1, vb); }
        const char* a = bufA0 + (c & 1) * TILEB;
        const char* bb = bufB0 + (c & 1) * TILEB;
#pragma unroll
        for (int kk = 0; kk < 2; kk++) {
            int kb = kk * 32 + tg * 4;
            uint32_t cH0 = (uint32_t)((kb     ) ^ mask);
            uint32_t cH1 = (uint32_t)((kb + 16) ^ mask);
            uint32_t cL0 = (uint32_t)((kb + 64) ^ mask);
            uint32_t cL1 = (uint32_t)((kb + 80) ^ mask);
            uint32_t ahi[4][4], alo[4][4], bhi[4][2], blo[4][2];
#pragma unroll
            for (int mt = 0; mt < 4; mt++) {
                int r0 = (wm*64 + mt*16 + g) * 128, r1 = r0 + 1024;
                ahi[mt][0] = *(const uint32_t*)(a + r0 + cH0);
                ahi[mt][1] = *(const uint32_t*)(a + r1 + cH0);
                ahi[mt][2] = *(const uint32_t*)(a + r0 + cH1);
                ahi[mt][3] = *(const uint32_t*)(a + r1 + cH1);
                alo[mt][0] = *(const uint32_t*)(a + r0 + cL0);
                alo[mt][1] = *(const uint32_t*)(a + r1 + cL0);
                alo[mt][2] = *(const uint32_t*)(a + r0 + cL1);
                alo[mt][3] = *(const uint32_t*)(a + r1 + cL1);
            }
#pragma unroll
            for (int nt = 0; nt < 4; nt++) {
                int rn = (wn*32 + nt*8 + g) * 128;
                bhi[nt][0] = *(const uint32_t*)(bb + rn + cH0);
                bhi[nt][1] = *(const uint32_t*)(bb + rn + cH1);
                blo[nt][0] = *(const uint32_t*)(bb + rn + cL0);
                blo[nt][1] = *(const uint32_t*)(bb + rn + cL1);
            }
#pragma unroll
            for (int mt = 0; mt < 4; mt++)
#pragma unroll
                for (int nt = 0; nt < 4; nt++) mma16816(acc[mt][nt], ahi[mt], bhi[nt]);
#pragma unroll
            for (int mt = 0; mt < 4; mt++)
#pragma unroll
                for (int nt = 0; nt < 4; nt++) mma16816(acc[mt][nt], alo[mt], bhi[nt]);
#pragma unroll
            for (int mt = 0; mt < 4; mt++)
#pragma unroll
                for (int nt = 0; nt < 4; nt++) mma16816(acc[mt][nt], ahi[mt], blo[nt]);
        }
        if (c + 1 < nch) {
            stsA((c + 1) & 1, va); stsB((c + 1) & 1, vb);
            __syncthreads();
        }
    }

    // ---- ZDIV prep: combine the two per-row zp halves, invert ----
    if (EX & 8) {
        red[tid] = zp;
        __syncthreads();
        if (tid < 128) {
            float z = red[tid] + red[tid + 128];
            aux[tid] = 1.0f / fmaxf(z, 1e-12f);
        }
        __syncthreads();
    }

    // ---- epilogue ----
    float rp[4][2], cs[4][2], cmn[4][2], cmx[4][2];
#pragma unroll
    for (int i = 0; i < 4; i++) {
        rp[i][0] = rp[i][1] = 0.f;
        cs[i][0] = cs[i][1] = 0.f;
        cmn[i][0] = cmn[i][1] = 1e30f;
        cmx[i][0] = cmx[i][1] = -1e30f;
    }
#pragma unroll
    for (int mt = 0; mt < 4; mt++) {
        int lr = wm*64 + mt*16 + g;
        int row = m0 + lr;
        float zi0 = 1.f, zi1 = 1.f;
        if (EX & 8) { zi0 = aux[lr]; zi1 = aux[lr + 8]; }
#pragma unroll
        for (int nt = 0; nt < 4; nt++) {
            int colL = wn*32 + nt*8 + tg*2;
            float c0 = acc[mt][nt][0], c1 = acc[mt][nt][1];
            float c2 = acc[mt][nt][2], c3 = acc[mt][nt][3];
            if (EX & 8) { c0 *= zi0; c1 *= zi0; c2 *= zi1; c3 *= zi1; }
            if (EP == 1) {
                float b0 = sbias[colL], b1 = sbias[colL + 1];
                c0 += b0; c1 += b1; c2 += b0; c3 += b1;
            }
            if (EP == 2) { c0 *= scale; c1 *= scale; c2 *= scale; c3 *= scale; }
            int col = n0 + colL;
            *(float2*)&Cb[(size_t)row * ldc + col]       = make_float2(c0, c1);
            *(float2*)&Cb[(size_t)(row + 8) * ldc + col] = make_float2(c2, c3);
            if (EX & 1) { cs[nt][0] += c0 + c2; cs[nt][1] += c1 + c3; }
            if (EX & 2) { rp[mt][0] += c0*c0 + c1*c1; rp[mt][1] += c2*c2 + c3*c3; }
            if (EX & 4) {
                cmn[nt][0] = fminf(cmn[nt][0], fminf(c0, c2));
                cmn[nt][1] = fminf(cmn[nt][1], fminf(c1, c3));
                cmx[nt][0] = fmaxf(cmx[nt][0], fmaxf(c0, c2));
                cmx[nt][1] = fmaxf(cmx[nt][1], fmaxf(c1, c3));
            }
        }
    }
    if (EX & 7) {
        if (EX & 1) {
#pragma unroll
            for (int nt = 0; nt < 4; nt++) {
                int colL = wn*32 + nt*8 + tg*2;
                atomicAdd(&scol[colL],     cs[nt][0]);
                atomicAdd(&scol[colL + 1], cs[nt][1]);
            }
        }
        if (EX & 2) {
#pragma unroll
            for (int mt = 0; mt < 4; mt++) {
                int lr = wm*64 + mt*16 + g;
                atomicAdd(&srow[lr],     rp[mt][0]);
                atomicAdd(&srow[lr + 8], rp[mt][1]);
            }
        }
        if (EX & 4) {
#pragma unroll
            for (int nt = 0; nt < 4; nt++) {
                int colL = wn*32 + nt*8 + tg*2;
                atomicMin(&smnU[colL],     encf(cmn[nt][0]));
                atomicMin(&smnU[colL + 1], encf(cmn[nt][1]));
                atomicMax(&smxU[colL],     encf(cmx[nt][0]));
                atomicMax(&smxU[colL + 1], encf(cmx[nt][1]));
            }
        }
        __syncthreads();
        if (tid < 128) {
            if (EX & 1) {
                float extra = (EP == 1) ? 128.f * sbias[tid] : 0.f;
                atomicAdd(&colsum[(size_t)b*DD + n0 + tid], scol[tid] + extra);
            }
            if (EX & 2) atomicAdd(&rowss[(size_t)b*SS + m0 + tid], srow[tid]);
            if (EX & 4) {
                atomicMin(&g_mnU[b*SS + n0 + tid], smnU[tid]);
                atomicMax(&g_mxU[b*SS + n0 + tid], smxU[tid]);
            }
        }
    }
}

// ---------------- GEMM wrappers ----------------
__global__ __launch_bounds__(256, 1) void k_patch(const float* __restrict__ img,
                                                  const float* __restrict__ Wv,
                                                  const float* __restrict__ bv) {
    tc_gemm<1,0,1,1,0>(img, Wv, g_patches, CC, HWN, DD, DD,
                       (size_t)CC*HWN, 0, (size_t)HWN*DD, bv, 1.f, g_psumV, nullptr);
}
__global__ __launch_bounds__(256, 1) void k_tok(const float* __restrict__ txt,
                                                const float* __restrict__ Wt,
                                                const float* __restrict__ bt) {
    tc_gemm<0,0,1,3,0>(txt, Wt, g_tokens, DD, DD, DD, DD,
                       (size_t)SS*DD, 0, (size_t)SS*DD, bt, 1.f, g_psumT, g_nt2);
}
__global__ __launch_bounds__(256, 1) void k_sim() {
    tc_gemm<0,0,0,4,0>(g_patches, g_tokens, g_sim, DD, DD, DD, SS,
                       (size_t)HWN*DD, (size_t)SS*DD, (size_t)HWN*SS, nullptr, 1.f,
                       nullptr, nullptr);
}
__global__ __launch_bounds__(256, 1) void k_lgve() {
    tc_gemm<2,1,0,10,0>(g_sim, g_patches, g_lgve, HWN, SS, DD, DD,
                        (size_t)HWN*SS, (size_t)HWN*DD, (size_t)SS*DD, nullptr, 1.f,
                        nullptr, g_nv2);
}
__global__ __launch_bounds__(256, 1) void k_fsim() {
    tc_gemm<0,0,2,0,1>(g_lgve, g_tokens, g_fsim, DD, DD, DD, SS,
                       (size_t)SS*DD, (size_t)SS*DD, (size_t)SS*SS, nullptr, 1.0f/TAUV,
                       nullptr, nullptr);
}

// ---------------- init accumulators ----------------
__global__ void k_init() {
    int i = blockIdx.x * 256 + threadIdx.x;   // grid 128 -> 32768 = BB*SS
    g_mnU[i] = 0xFFFFFFFFu;
    g_mxU[i] = 0u;
    g_nv2[i] = 0.f;
    g_nt2[i] = 0.f;
    if (i < BB*DD) { g_psumV[i] = 0.f; g_psumT[i] = 0.f; }
}

// ---------------- global adapters (warp-dot GEMV) ----------------
__global__ void k_gimg(const float* __restrict__ Wv, const float* __restrict__ bv) {
    __shared__ float sm[DD];
    int b = blockIdx.x;
    int warp = threadIdx.x >> 5, lane = threadIdx.x & 31;
    for (int c = threadIdx.x; c < DD; c += 256)
        sm[c] = g_psumV[b*DD + c] * (1.0f / (float)HWN);
    __syncthreads();
    for (int i = 0; i < 32; i++) {
        int d = warp * 32 + i;
        const float* wr = Wv + (size_t)d * DD;
        float s = 0.f;
#pragma unroll
        for (int q = 0; q < 8; q++) s += sm[lane + q*32] * wr[lane + q*32];
#pragma unroll
        for (int off = 16; off > 0; off >>= 1) s += __shfl_xor_sync(0xffffffffu, s, off);
        if (lane == 0) g_gimg[b*DD + d] = s + bv[d];
    }
}
__global__ void k_gtxt(const float* __restrict__ Wt, const float* __restrict__ bt) {
    __shared__ float sm[DD];
    int b = blockIdx.x;
    int warp = threadIdx.x >> 5, lane = threadIdx.x & 31;
    for (int c = threadIdx.x; c < DD; c += 256)
        sm[c] = g_psumT[b*DD + c] * (1.0f / (float)SS);
    __syncthreads();
    for (int i = 0; i < 32; i++) {
        int d = warp * 32 + i;
        const float* wr = Wt + (size_t)d * DD;
        float s = 0.f;
#pragma unroll
        for (int q = 0; q < 8; q++) s += sm[lane + q*32] * wr[lane + q*32];
#pragma unroll
        for (int off = 16; off > 0; off >>= 1) s += __shfl_xor_sync(0xffffffffu, s, off);
        if (lane == 0) g_gtxt[b*DD + d] = s + bt[d];
    }
}

// ---------------- global embedding norms ----------------
__global__ void k_gnorm() {
    int r = blockIdx.x, lane = threadIdx.x;
    const float* row = (r < 64) ? (g_gimg + (size_t)r * DD)
                                : (g_gtxt + (size_t)(r - 64) * DD);
    float s = 0.f;
#pragma unroll
    for (int q = 0; q < 8; q++) { float v = row[lane + q*32]; s += v*v; }
#pragma unroll
    for (int off = 16; off > 0; off >>= 1) s += __shfl_xor_sync(0xffffffffu, s, off);
    if (lane == 0) g_norms[r] = fmaxf(sqrtf(s), 1e-8f);
}

// ---------------- global sim matrix 64x64 ----------------
__global__ void k_gsim() {
    __shared__ float srow[DD];
    int i = blockIdx.x;
    int warp = threadIdx.x >> 5, lane = threadIdx.x & 31;
    for (int c = threadIdx.x; c < DD; c += 256) srow[c] = g_gimg[(size_t)i * DD + c];
    __syncthreads();
    float ni = g_norms[i];
    for (int j = warp; j < 64; j += 8) {
        const float* trow = g_gtxt + (size_t)j * DD;
        float s = 0.f;
#pragma unroll
        for (int q = 0; q < 8; q++) s += srow[lane + q*32] * trow[lane + q*32];
#pragma unroll
        for (int off = 16; off > 0; off >>= 1) s += __shfl_xor_sync(0xffffffffu, s, off);
        if (lane == 0)
            g_gsim[i*64 + j] = s / (ni * g_norms[64 + j]) * (1.0f / TAUV);
    }
}

// ---------------- global loss ----------------
__global__ void k_gloss() {
    __shared__ float sim[64][65];
    __shared__ float r1[64], r2[64];
    int t = threadIdx.x;  // 64 threads
    for (int idx = t; idx < 4096; idx += 64) sim[idx >> 6][idx & 63] = g_gsim[idx];
    __syncthreads();
    float m = -1e30f;
    for (int j = 0; j < 64; j++) m = fmaxf(m, sim[t][j]);
    float s = 0.f;
    for (int j = 0; j < 64; j++) s += expf(sim[t][j] - m);
    r1[t] = m + logf(s) - sim[t][t];
    m = -1e30f;
    for (int i = 0; i < 64; i++) m = fmaxf(m, sim[i][t]);
    s = 0.f;
    for (int i = 0; i < 64; i++) s += expf(sim[i][t] - m);
    r2[t] = m + logf(s) - sim[t][t];
    __syncthreads();
    if (t == 0) {
        float acc = 0.f;
        for (int r = 0; r < 64; r++) acc += r1[r] + r2[r];
        g_gloss = 0.5f * acc / 64.0f;
    }
}

// ---------------- fsim row / col LSE terms ----------------
__global__ void k_frow() {
    int warp = threadIdx.x >> 5, lane = threadIdx.x & 31;
    int r = blockIdx.x * 8 + warp;
    int b = r >> 9, i = r & (SS - 1);
    const float* row = g_fsim + ((size_t)b * SS + i) * SS;
    float v[16];
#pragma unroll
    for (int q = 0; q < 16; q++) v[q] = row[lane + q*32];
    float m = -1e30f;
#pragma unroll
    for (int q = 0; q < 16; q++) m = fmaxf(m, v[q]);
#pragma unroll
    for (int off = 16; off > 0; off >>= 1) m = fmaxf(m, __shfl_xor_sync(0xffffffffu, m, off));
    float s = 0.f;
#pragma unroll
    for (int q = 0; q < 16; q++) s += expf(v[q] - m);
#pragma unroll
    for (int off = 16; off > 0; off >>= 1) s += __shfl_xor_sync(0xffffffffu, s, off);
    if (lane == 0) g_rowterm[r] = m + logf(s) - row[i];
}

__global__ void k_fcol() {
    int b = blockIdx.y;
    int tx = threadIdx.x, ty = threadIdx.y;
    int j = blockIdx.x * 32 + tx;
    const float* Fb = g_fsim + (size_t)b * SS * SS;
    float m = -1e30f, s = 0.f;
    for (int i = ty; i < SS; i += 8) {
        float x = Fb[(size_t)i * SS + j];
        float nm = fmaxf(m, x);
        s = s * expf(m - nm) + expf(x - nm);
        m = nm;
    }
    __shared__ float sm[8][32], sv[8][32];
    sm[ty][tx] = m; sv[ty][tx] = s;
    __syncthreads();
    if (ty == 0) {
        float M = sm[0][tx], Sv = sv[0][tx];
#pragma unroll
        for (int q = 1; q < 8; q++) {
            float m2 = sm[q][tx], s2 = sv[q][tx];
            float nm = fmaxf(M, m2);
            Sv = Sv * expf(M - nm) + s2 * expf(m2 - nm);
            M = nm;
        }
        g_colterm[b*SS + j] = M + logf(Sv) - Fb[(size_t)j * SS + j];
    }
}

// ---------------- final scalar ----------------
__global__ void k_final(float* out) {
    __shared__ float red[256];
    int t = threadIdx.x;
    float s = 0.f;
    for (int idx = t; idx < BB*SS; idx += 256) s += g_rowterm[idx] + g_colterm[idx];
    red[t] = s;
    __syncthreads();
    for (int o = 128; o > 0; o >>= 1) {
        if (t < o) red[t] += red[t + o];
        __syncthreads();
    }
    if (t == 0) out[0] = g_gloss + 0.5f * red[0] / (float)(BB*SS);
}

// ---------------- launch ----------------
extern "C" void kernel_launch(void* const* d_in, const int* in_sizes, int n_in,
                              void* d_out, int out_size) {
    const float* img = (const float*)d_in[0];
    const float* txt = (const float*)d_in[1];
    const float* Wv  = (const float*)d_in[2];
    const float* bv  = (const float*)d_in[3];
    const float* Wt  = (const float*)d_in[4];
    const float* bt  = (const float*)d_in[5];
    float* out = (float*)d_out;

    static int attr_done = 0;
    if (!attr_done) {
        cudaFuncSetAttribute(k_patch, cudaFuncAttributeMaxDynamicSharedMemorySize, SMEMSZ);
        cudaFuncSetAttribute(k_tok,   cudaFuncAttributeMaxDynamicSharedMemorySize, SMEMSZ);
        cudaFuncSetAttribute(k_sim,   cudaFuncAttributeMaxDynamicSharedMemorySize, SMEMSZ);
        cudaFuncSetAttribute(k_lgve,  cudaFuncAttributeMaxDynamicSharedMemorySize, SMEMSZ);
        cudaFuncSetAttribute(k_fsim,  cudaFuncAttributeMaxDynamicSharedMemorySize, SMEMSZ);
        attr_done = 1;
    }

    k_init <<<128, 256>>>();                                 // 1
    k_patch<<<dim3(8, 2, BB), 256, SMEMSZ>>>(img, Wv, bv);   // 2 (+colsum)
    k_tok  <<<dim3(4, 2, BB), 256, SMEMSZ>>>(txt, Wt, bt);   // 3 (+colsum, rowss)
    k_gimg <<<BB, 256>>>(Wv, bv);                            // 4
    k_gtxt <<<BB, 256>>>(Wt, bt);                            // 5
    k_sim  <<<dim3(8, 4, BB), 256, SMEMSZ>>>();              // 6  <- ncu target (+minmax)
    k_gnorm<<<128, 32>>>();                                  // 7
    k_gsim <<<64, 256>>>();                                  // 8
    k_gloss<<<1, 64>>>();                                    // 9
    k_lgve <<<dim3(4, 2, BB), 256, SMEMSZ>>>();              // 10 (zdiv + rowss)
    k_fsim <<<dim3(4, 4, BB), 256, SMEMSZ>>>();              // 11 (normalized staging)
    k_frow <<<(BB*SS)/8, 256>>>();
    k_fcol <<<dim3(SS/32, BB), dim3(32, 8)>>>();
    k_final<<<1, 256>>>(out);
}

// round 13
// speedup vs baseline: 1.0384x; 1.0384x over previous
#include <cuda_runtime.h>
#include <cuda_bf16.h>
#include <math.h>
#include <stdint.h>

// Problem dims
#define BB 64
#define CC 256
#define HWN 1024
#define SS 512
#define DD 256
#define TAUV 0.07f
#define SIGMA (1.0f/1024.0f)

// ---------------- scratch (static device globals; no allocation) ----------------
__device__ float g_patches[(size_t)BB*HWN*DD];   // 64 MB  [b][p][d]
__device__ float g_tokens [(size_t)BB*SS*DD];    // 32 MB  [b][s][d]
__device__ float g_sim    [(size_t)BB*HWN*SS];   // 128 MB [b][p][s]
__device__ float g_lgve   [(size_t)BB*SS*DD];    // 32 MB
__device__ float g_fsim   [(size_t)BB*SS*SS];    // 64 MB  [b][i][j]
__device__ float    g_psumV[BB*DD];   // column sums of patches (mean-pool)
__device__ float    g_psumT[BB*DD];
__device__ float    g_nv2[BB*SS];     // lgve row sumsq
__device__ float    g_nt2[BB*SS];     // tokens row sumsq
__device__ uint32_t g_mnU[BB*SS];     // sim column min (encoded)
__device__ uint32_t g_mxU[BB*SS];     // sim column max (encoded)
__device__ float g_gimg[BB*DD];
__device__ float g_gtxt[BB*DD];
__device__ float g_norms[128];
__device__ float g_gsim[64*64];
__device__ float g_rowterm[BB*SS];
__device__ float g_colterm[BB*SS];
__device__ float g_gloss;

// ---------------- helpers ----------------
__device__ __forceinline__ uint32_t encf(float f) {
    uint32_t u = __float_as_uint(f);
    return ((int)u < 0) ? ~u : (u | 0x80000000u);
}
__device__ __forceinline__ float decf(uint32_t u) {
    return ((int)u < 0) ? __uint_as_float(u & 0x7fffffffu) : __uint_as_float(~u);
}
__device__ __forceinline__ uint32_t smem_u32(const void* p) {
    uint32_t a;
    asm("{ .reg .u64 t; cvta.to.shared.u64 t, %1; cvt.u32.u64 %0, t; }" : "=r"(a) : "l"(p));
    return a;
}

// bf16 hi/lo split of a pair -> packed bf16x2 words (x0 in low half)
__device__ __forceinline__ void split_pair(float x0, float x1, uint32_t& h, uint32_t& l) {
    asm("cvt.rn.bf16x2.f32 %0, %1, %2;" : "=r"(h) : "f"(x1), "f"(x0));
    float f0 = __uint_as_float(h << 16);           // bf16(x0)
    float f1 = __uint_as_float(h & 0xffff0000u);   // bf16(x1)
    asm("cvt.rn.bf16x2.f32 %0, %1, %2;" : "=r"(l) : "f"(x1 - f1), "f"(x0 - f0));
}

__device__ __forceinline__ void mma16816(float* c, const uint32_t* a, const uint32_t* b2) {
    asm volatile(
        "mma.sync.aligned.m16n8k16.row.col.f32.bf16.bf16.f32 "
        "{%0,%1,%2,%3},{%4,%5,%6,%7},{%8,%9},{%0,%1,%2,%3};"
        : "+f"(c[0]), "+f"(c[1]), "+f"(c[2]), "+f"(c[3])
        : "r"(a[0]), "r"(a[1]), "r"(a[2]), "r"(a[3]), "r"(b2[0]), "r"(b2[1]));
}

__device__ __forceinline__ void ldsm4(uint32_t* r, uint32_t addr) {
    asm volatile("ldmatrix.sync.aligned.m8n8.x4.shared.b16 {%0,%1,%2,%3}, [%4];"
        : "=r"(r[0]), "=r"(r[1]), "=r"(r[2]), "=r"(r[3]) : "r"(addr));
}

// SMEM layout (dynamic):
//   [0,512)        bias (128 floats)
//   [512,1536)     red: 256 floats (ZDIV zpart) / 2x128 uints (MINMAX)
//   [1536,2048)    aux: 128 floats (ZDIV zinv / COLSUM scol)
//   [2048,2560)    srow: 128 floats (ROWSS)
//   [2560, +64K)   A/B double buffers
#define OFF_RED  512
#define OFF_AUX  1536
#define OFF_ROW  2048
#define OFF_AB   2560
#define TILEB    16384
#define SMEMSZ   (2560 + 4*16384)

// EX bits: 1=COLSUM, 2=ROWSS, 4=MINMAX, 8=ZDIV
// AMODE: 0 = A[m][k] row-major; 1 = A[k][m]; 2 = mode1 + lgve weight xform
// BMODE: 0 = B[n][k] row-major; 1 = B[k][n]
// EP:    0 plain; 1 +bias[n]; 2 *scale
// NRM:   1 = L2-normalize A rows by g_nv2, B rows by g_nt2 during staging (fsim)
template<int AMODE, int BMODE, int EP, int EX, int NRM>
__device__ __forceinline__ void tc_gemm(
    const float* __restrict__ A, const float* __restrict__ B, float* __restrict__ C,
    int K, int lda, int ldb, int ldc, size_t sA, size_t sB, size_t sC,
    const float* __restrict__ bias, float scale,
    float* __restrict__ colsum, float* __restrict__ rowss)
{
    extern __shared__ char smem[];
    float* sbias = (float*)smem;
    float* red   = (float*)(smem + OFF_RED);
    float* aux   = (float*)(smem + OFF_AUX);
    float* srow  = (float*)(smem + OFF_ROW);
    uint32_t* smnU = (uint32_t*)(smem + OFF_RED);
    uint32_t* smxU = (uint32_t*)(smem + OFF_RED + 512);
    float* scol  = (float*)(smem + OFF_AUX);
    char* bufA0 = smem + OFF_AB;
    char* bufB0 = smem + OFF_AB + 2*TILEB;
    uint32_t sAB = smem_u32(smem) + OFF_AB;

    int tid = threadIdx.x, lane = tid & 31, wid = tid >> 5;
    int g = lane >> 2, tg = lane & 3;
    int wm = wid & 1, wn = wid >> 1;       // 2 x 4 warp grid; warp tile 64x32
    int b = blockIdx.z;
    int m0 = blockIdx.x * 128, n0 = blockIdx.y * 128;

    const float* Abase = (AMODE == 0) ? (A + (size_t)b*sA + (size_t)m0*lda)
                                      : (A + (size_t)b*sA + m0);
    const float* Bbase = (BMODE == 0) ? (B + (size_t)b*sB + (size_t)n0*ldb)
                                      : (B + (size_t)b*sB + n0);
    float* Cb = C + (size_t)b*sC;

    if (EP == 1 && tid < 128) sbias[tid] = bias[n0 + tid];
    if ((EX & 1) && tid < 128) scol[tid] = 0.f;
    if ((EX & 2) && tid < 128) srow[tid] = 0.f;
    if ((EX & 4) && tid < 128) { smnU[tid] = 0xFFFFFFFFu; smxU[tid] = 0u; }

    // staging maps
    const int aRow = (AMODE == 0) ? (tid >> 1) : (tid & 127);
    const int aSeg = (AMODE == 0) ? ((tid & 1) * 16) : ((tid >> 7) * 16);
    const int bRow = (BMODE == 0) ? (tid >> 1) : (tid & 127);
    const int bSeg = (BMODE == 0) ? ((tid & 1) * 16) : ((tid >> 7) * 16);

    // ldmatrix lane geometry (per-warp constants)
    const uint32_t aRowL = (uint32_t)(wm*64 + (lane & 15));
    const uint32_t aColL = (uint32_t)((lane >> 4) << 4);        // 0 | 16
    const uint32_t aMask = (uint32_t)((lane & 7) << 4);
    const uint32_t bRowL = (uint32_t)(wn*32 + (lane & 7) + ((lane & 16) >> 1));
    const uint32_t bColL = (uint32_t)((lane & 8) << 1);         // 0 | 16
    const uint32_t bMask = (uint32_t)((lane & 7) << 4);

    float xmn = 0.f, xri = 0.f, zp = 0.f;
    if (AMODE == 2) {
        float mn = decf(g_mnU[b*SS + m0 + aRow]);
        float mx = decf(g_mxU[b*SS + m0 + aRow]);
        xmn = mn; xri = 1.0f / (mx - mn + 1e-8f);
    }
    float invA = 1.f, invB = 1.f;
    if (NRM) {
        invA = 1.0f / fmaxf(sqrtf(g_nv2[b*SS + m0 + aRow]), 1e-8f);
        invB = 1.0f / fmaxf(sqrtf(g_nt2[b*SS + n0 + bRow]), 1e-8f);
    }

    float acc[4][4][4];
#pragma unroll
    for (int i = 0; i < 4; i++)
#pragma unroll
        for (int j = 0; j < 4; j++)
#pragma unroll
            for (int q = 0; q < 4; q++) acc[i][j][q] = 0.f;

    auto ldgA = [&](int c, float* v) {
        if (AMODE == 0) {
            const float* p = Abase + (size_t)aRow * lda + c*32 + aSeg;
            *(float4*)(v+0)  = *(const float4*)(p+0);
            *(float4*)(v+4)  = *(const float4*)(p+4);
            *(float4*)(v+8)  = *(const float4*)(p+8);
            *(float4*)(v+12) = *(const float4*)(p+12);
        } else {
            const float* p = Abase + (size_t)(c*32 + aSeg) * lda + aRow;
#pragma unroll
            for (int q = 0; q < 16; q++) v[q] = p[(size_t)q * lda];
        }
    };
    auto ldgB = [&](int c, float* v) {
        if (BMODE == 0) {
            const float* p = Bbase + (size_t)bRow * ldb + c*32 + bSeg;
            *(float4*)(v+0)  = *(const float4*)(p+0);
            *(float4*)(v+4)  = *(const float4*)(p+4);
            *(float4*)(v+8)  = *(const float4*)(p+8);
            *(float4*)(v+12) = *(const float4*)(p+12);
        } else {
            const float* p = Bbase + (size_t)(c*32 + bSeg) * ldb + bRow;
#pragma unroll
            for (int q = 0; q < 16; q++) v[q] = p[(size_t)q * ldb];
        }
    };
    auto stsA = [&](int buf, float* v) {
        if (AMODE == 2) {
#pragma unroll
            for (int q = 0; q < 16; q++) {
                float t = (v[q] - xmn) * xri;
                t = (t < SIGMA) ? 0.f : t;
                zp += t;
                v[q] = t;
            }
        }
        if (NRM) {
#pragma unroll
            for (int q = 0; q < 16; q++) v[q] *= invA;
        }
        uint32_t h[8], l[8];
#pragma unroll
        for (int q = 0; q < 8; q++) split_pair(v[2*q], v[2*q+1], h[q], l[q]);
        char* dst = bufA0 + buf*TILEB + aRow*128;
        int mask = (aRow & 7) << 4, cb = aSeg * 2;
        *(uint4*)(dst + ((cb     ) ^ mask)) = make_uint4(h[0], h[1], h[2], h[3]);
        *(uint4*)(dst + ((cb + 16) ^ mask)) = make_uint4(h[4], h[5], h[6], h[7]);
        *(uint4*)(dst + ((cb + 64) ^ mask)) = make_uint4(l[0], l[1], l[2], l[3]);
        *(uint4*)(dst + ((cb + 80) ^ mask)) = make_uint4(l[4], l[5], l[6], l[7]);
    };
    auto stsB = [&](int buf, float* v) {
        if (NRM) {
#pragma unroll
            for (int q = 0; q < 16; q++) v[q] *= invB;
        }
        uint32_t h[8], l[8];
#pragma unroll
        for (int q = 0; q < 8; q++) split_pair(v[2*q], v[2*q+1], h[q], l[q]);
        char* dst = bufB0 + buf*TILEB + bRow*128;
        int mask = (bRow & 7) << 4, cb = bSeg * 2;
        *(uint4*)(dst + ((cb     ) ^ mask)) = make_uint4(h[0], h[1], h[2], h[3]);
        *(uint4*)(dst + ((cb + 16) ^ mask)) = make_uint4(h[4], h[5], h[6], h[7]);
        *(uint4*)(dst + ((cb + 64) ^ mask)) = make_uint4(l[0], l[1], l[2], l[3]);
        *(uint4*)(dst + ((cb + 80) ^ mask)) = make_uint4(l[4], l[5], l[6], l[7]);
    };

    float va[16], vb[16];
    ldgA(0, va); ldgB(0, vb);
    stsA(0, va); stsB(0, vb);
    __syncthreads();

    const int nch = K / 32;
    for (int c = 0; c < nch; c++) {
        if (c + 1 < nch) { ldgA(c + 1, va); ldgB(c + 1, vb); }
        const uint32_t aB = sAB + (c & 1)*TILEB + aRowL*128;
        const uint32_t bB = sAB + 2*TILEB + (c & 1)*TILEB + bRowL*128;
#pragma unroll
        for (int kk = 0; kk < 2; kk++) {
            uint32_t ah[4][4], al[4][4], bh[4][2], bl[4][2];
            uint32_t aCh = (aColL + kk*32) ^ aMask;
            uint32_t aCl = (aColL + kk*32 + 64) ^ aMask;
            uint32_t bCh = (bColL + kk*32) ^ bMask;
            uint32_t bCl = (bColL + kk*32 + 64) ^ bMask;
#pragma unroll
            for (int mt = 0; mt < 4; mt++) {
                ldsm4(ah[mt], aB + mt*2048 + aCh);
                ldsm4(al[mt], aB + mt*2048 + aCl);
            }
#pragma unroll
            for (int p = 0; p < 2; p++) {
                uint32_t r[4];
                ldsm4(r, bB + p*2048 + bCh);
                bh[2*p][0] = r[0]; bh[2*p][1] = r[1];
                bh[2*p+1][0] = r[2]; bh[2*p+1][1] = r[3];
                ldsm4(r, bB + p*2048 + bCl);
                bl[2*p][0] = r[0]; bl[2*p][1] = r[1];
                bl[2*p+1][0] = r[2]; bl[2*p+1][1] = r[3];
            }
#pragma unroll
            for (int mt = 0; mt < 4; mt++)
#pragma unroll
                for (int nt = 0; nt < 4; nt++) mma16816(acc[mt][nt], ah[mt], bh[nt]);
#pragma unroll
            for (int mt = 0; mt < 4; mt++)
#pragma unroll
                for (int nt = 0; nt < 4; nt++) mma16816(acc[mt][nt], al[mt], bh[nt]);
#pragma unroll
            for (int mt = 0; mt < 4; mt++)
#pragma unroll
                for (int nt = 0; nt < 4; nt++) mma16816(acc[mt][nt], ah[mt], bl[nt]);
        }
        if (c + 1 < nch) {
            stsA((c + 1) & 1, va); stsB((c + 1) & 1, vb);
            __syncthreads();
        }
    }

    // ---- ZDIV prep: combine the two per-row zp halves, invert ----
    if (EX & 8) {
        red[tid] = zp;
        __syncthreads();
        if (tid < 128) {
            float z = red[tid] + red[tid + 128];
            aux[tid] = 1.0f / fmaxf(z, 1e-12f);
        }
        __syncthreads();
    }

    // ---- epilogue ----
    float rp[4][2], cs[4][2], cmn[4][2], cmx[4][2];
#pragma unroll
    for (int i = 0; i < 4; i++) {
        rp[i][0] = rp[i][1] = 0.f;
        cs[i][0] = cs[i][1] = 0.f;
        cmn[i][0] = cmn[i][1] = 1e30f;
        cmx[i][0] = cmx[i][1] = -1e30f;
    }
#pragma unroll
    for (int mt = 0; mt < 4; mt++) {
        int lr = wm*64 + mt*16 + g;
        int row = m0 + lr;
        float zi0 = 1.f, zi1 = 1.f;
        if (EX & 8) { zi0 = aux[lr]; zi1 = aux[lr + 8]; }
#pragma unroll
        for (int nt = 0; nt < 4; nt++) {
            int colL = wn*32 + nt*8 + tg*2;
            float c0 = acc[mt][nt][0], c1 = acc[mt][nt][1];
            float c2 = acc[mt][nt][2], c3 = acc[mt][nt][3];
            if (EX & 8) { c0 *= zi0; c1 *= zi0; c2 *= zi1; c3 *= zi1; }
            if (EP == 1) {
                float b0 = sbias[colL], b1 = sbias[colL + 1];
                c0 += b0; c1 += b1; c2 += b0; c3 += b1;
            }
            if (EP == 2) { c0 *= scale; c1 *= scale; c2 *= scale; c3 *= scale; }
            int col = n0 + colL;
            *(float2*)&Cb[(size_t)row * ldc + col]       = make_float2(c0, c1);
            *(float2*)&Cb[(size_t)(row + 8) * ldc + col] = make_float2(c2, c3);
            if (EX & 1) { cs[nt][0] += c0 + c2; cs[nt][1] += c1 + c3; }
            if (EX & 2) { rp[mt][0] += c0*c0 + c1*c1; rp[mt][1] += c2*c2 + c3*c3; }
            if (EX & 4) {
                cmn[nt][0] = fminf(cmn[nt][0], fminf(c0, c2));
                cmn[nt][1] = fminf(cmn[nt][1], fminf(c1, c3));
                cmx[nt][0] = fmaxf(cmx[nt][0], fmaxf(c0, c2));
                cmx[nt][1] = fmaxf(cmx[nt][1], fmaxf(c1, c3));
            }
        }
    }
    if (EX & 7) {
        if (EX & 1) {
#pragma unroll
            for (int nt = 0; nt < 4; nt++) {
                int colL = wn*32 + nt*8 + tg*2;
                atomicAdd(&scol[colL],     cs[nt][0]);
                atomicAdd(&scol[colL + 1], cs[nt][1]);
            }
        }
        if (EX & 2) {
#pragma unroll
            for (int mt = 0; mt < 4; mt++) {
                int lr = wm*64 + mt*16 + g;
                atomicAdd(&srow[lr],     rp[mt][0]);
                atomicAdd(&srow[lr + 8], rp[mt][1]);
            }
        }
        if (EX & 4) {
#pragma unroll
            for (int nt = 0; nt < 4; nt++) {
                int colL = wn*32 + nt*8 + tg*2;
                atomicMin(&smnU[colL],     encf(cmn[nt][0]));
                atomicMin(&smnU[colL + 1], encf(cmn[nt][1]));
                atomicMax(&smxU[colL],     encf(cmx[nt][0]));
                atomicMax(&smxU[colL + 1], encf(cmx[nt][1]));
            }
        }
        __syncthreads();
        if (tid < 128) {
            if (EX & 1) {
                float extra = (EP == 1) ? 128.f * sbias[tid] : 0.f;
                atomicAdd(&colsum[(size_t)b*DD + n0 + tid], scol[tid] + extra);
            }
            if (EX & 2) atomicAdd(&rowss[(size_t)b*SS + m0 + tid], srow[tid]);
            if (EX & 4) {
                atomicMin(&g_mnU[b*SS + n0 + tid], smnU[tid]);
                atomicMax(&g_mxU[b*SS + n0 + tid], smxU[tid]);
            }
        }
    }
}

// ---------------- GEMM wrappers ----------------
__global__ __launch_bounds__(256, 1) void k_patch(const float* __restrict__ img,
                                                  const float* __restrict__ Wv,
                                                  const float* __restrict__ bv) {
    tc_gemm<1,0,1,1,0>(img, Wv, g_patches, CC, HWN, DD, DD,
                       (size_t)CC*HWN, 0, (size_t)HWN*DD, bv, 1.f, g_psumV, nullptr);
}
__global__ __launch_bounds__(256, 1) void k_tok(const float* __restrict__ txt,
                                                const float* __restrict__ Wt,
                                                const float* __restrict__ bt) {
    tc_gemm<0,0,1,3,0>(txt, Wt, g_tokens, DD, DD, DD, DD,
                       (size_t)SS*DD, 0, (size_t)SS*DD, bt, 1.f, g_psumT, g_nt2);
}
__global__ __launch_bounds__(256, 1) void k_sim() {
    tc_gemm<0,0,0,4,0>(g_patches, g_tokens, g_sim, DD, DD, DD, SS,
                       (size_t)HWN*DD, (size_t)SS*DD, (size_t)HWN*SS, nullptr, 1.f,
                       nullptr, nullptr);
}
__global__ __launch_bounds__(256, 1) void k_lgve() {
    tc_gemm<2,1,0,10,0>(g_sim, g_patches, g_lgve, HWN, SS, DD, DD,
                        (size_t)HWN*SS, (size_t)HWN*DD, (size_t)SS*DD, nullptr, 1.f,
                        nullptr, g_nv2);
}
__global__ __launch_bounds__(256, 1) void k_fsim() {
    tc_gemm<0,0,2,0,1>(g_lgve, g_tokens, g_fsim, DD, DD, DD, SS,
                       (size_t)SS*DD, (size_t)SS*DD, (size_t)SS*SS, nullptr, 1.0f/TAUV,
                       nullptr, nullptr);
}

// ---------------- init accumulators ----------------
__global__ void k_init() {
    int i = blockIdx.x * 256 + threadIdx.x;   // grid 128 -> 32768 = BB*SS
    g_mnU[i] = 0xFFFFFFFFu;
    g_mxU[i] = 0u;
    g_nv2[i] = 0.f;
    g_nt2[i] = 0.f;
    if (i < BB*DD) { g_psumV[i] = 0.f; g_psumT[i] = 0.f; }
}

// ---------------- global adapters (warp-dot GEMV, spread grid) ----------------
__global__ void k_gimg(const float* __restrict__ Wv, const float* __restrict__ bv) {
    __shared__ float sm[DD];
    int b = blockIdx.y, d0 = blockIdx.x * 32;
    int warp = threadIdx.x >> 5, lane = threadIdx.x & 31;
    for (int c = threadIdx.x; c < DD; c += 256)
        sm[c] = g_psumV[b*DD + c] * (1.0f / (float)HWN);
    __syncthreads();
#pragma unroll
    for (int i = 0; i < 4; i++) {
        int d = d0 + warp * 4 + i;
        const float* wr = Wv + (size_t)d * DD;
        float s = 0.f;
#pragma unroll
        for (int q = 0; q < 8; q++) s += sm[lane + q*32] * wr[lane + q*32];
#pragma unroll
        for (int off = 16; off > 0; off >>= 1) s += __shfl_xor_sync(0xffffffffu, s, off);
        if (lane == 0) g_gimg[b*DD + d] = s + bv[d];
    }
}
__global__ void k_gtxt(const float* __restrict__ Wt, const float* __restrict__ bt) {
    __shared__ float sm[DD];
    int b = blockIdx.y, d0 = blockIdx.x * 32;
    int warp = threadIdx.x >> 5, lane = threadIdx.x & 31;
    for (int c = threadIdx.x; c < DD; c += 256)
        sm[c] = g_psumT[b*DD + c] * (1.0f / (float)SS);
    __syncthreads();
#pragma unroll
    for (int i = 0; i < 4; i++) {
        int d = d0 + warp * 4 + i;
        const float* wr = Wt + (size_t)d * DD;
        float s = 0.f;
#pragma unroll
        for (int q = 0; q < 8; q++) s += sm[lane + q*32] * wr[lane + q*32];
#pragma unroll
        for (int off = 16; off > 0; off >>= 1) s += __shfl_xor_sync(0xffffffffu, s, off);
        if (lane == 0) g_gtxt[b*DD + d] = s + bt[d];
    }
}

// ---------------- global embedding norms ----------------
__global__ void k_gnorm() {
    int r = blockIdx.x, lane = threadIdx.x;
    const float* row = (r < 64) ? (g_gimg + (size_t)r * DD)
                                : (g_gtxt + (size_t)(r - 64) * DD);
    float s = 0.f;
#pragma unroll
    for (int q = 0; q < 8; q++) { float v = row[lane + q*32]; s += v*v; }
#pragma unroll
    for (int off = 16; off > 0; off >>= 1) s += __shfl_xor_sync(0xffffffffu, s, off);
    if (lane == 0) g_norms[r] = fmaxf(sqrtf(s), 1e-8f);
}

// ---------------- global sim matrix 64x64 ----------------
__global__ void k_gsim() {
    __shared__ float srow[DD];
    int i = blockIdx.x;
    int warp = threadIdx.x >> 5, lane = threadIdx.x & 31;
    for (int c = threadIdx.x; c < DD; c += 256) srow[c] = g_gimg[(size_t)i * DD + c];
    __syncthreads();
    float ni = g_norms[i];
    for (int j = warp; j < 64; j += 8) {
        const float* trow = g_gtxt + (size_t)j * DD;
        float s = 0.f;
#pragma unroll
        for (int q = 0; q < 8; q++) s += srow[lane + q*32] * trow[lane + q*32];
#pragma unroll
        for (int off = 16; off > 0; off >>= 1) s += __shfl_xor_sync(0xffffffffu, s, off);
        if (lane == 0)
            g_gsim[i*64 + j] = s / (ni * g_norms[64 + j]) * (1.0f / TAUV);
    }
}

// ---------------- global loss ----------------
__global__ void k_gloss() {
    __shared__ float sim[64][65];
    __shared__ float r1[64], r2[64];
    int t = threadIdx.x;  // 64 threads
    for (int idx = t; idx < 4096; idx += 64) sim[idx >> 6][idx & 63] = g_gsim[idx];
    __syncthreads();
    float m = -1e30f;
    for (int j = 0; j < 64; j++) m = fmaxf(m, sim[t][j]);
    float s = 0.f;
    for (int j = 0; j < 64; j++) s += expf(sim[t][j] - m);
    r1[t] = m + logf(s) - sim[t][t];
    m = -1e30f;
    for (int i = 0; i < 64; i++) m = fmaxf(m, sim[i][t]);
    s = 0.f;
    for (int i = 0; i < 64; i++) s += expf(sim[i][t] - m);
    r2[t] = m + logf(s) - sim[t][t];
    __syncthreads();
    if (t == 0) {
        float acc = 0.f;
        for (int r = 0; r < 64; r++) acc += r1[r] + r2[r];
        g_gloss = 0.5f * acc / 64.0f;
    }
}

// ---------------- fsim row / col LSE terms ----------------
__global__ void k_frow() {
    int warp = threadIdx.x >> 5, lane = threadIdx.x & 31;
    int r = blockIdx.x * 8 + warp;
    int b = r >> 9, i = r & (SS - 1);
    const float* row = g_fsim + ((size_t)b * SS + i) * SS;
    float v[16];
#pragma unroll
    for (int q = 0; q < 16; q++) v[q] = row[lane + q*32];
    float m = -1e30f;
#pragma unroll
    for (int q = 0; q < 16; q++) m = fmaxf(m, v[q]);
#pragma unroll
    for (int off = 16; off > 0; off >>= 1) m = fmaxf(m, __shfl_xor_sync(0xffffffffu, m, off));
    float s = 0.f;
#pragma unroll
    for (int q = 0; q < 16; q++) s += expf(v[q] - m);
#pragma unroll
    for (int off = 16; off > 0; off >>= 1) s += __shfl_xor_sync(0xffffffffu, s, off);
    if (lane == 0) g_rowterm[r] = m + logf(s) - row[i];
}

__global__ void k_fcol() {
    int b = blockIdx.y;
    int tx = threadIdx.x, ty = threadIdx.y;
    int j = blockIdx.x * 32 + tx;
    const float* Fb = g_fsim + (size_t)b * SS * SS;
    float m = -1e30f, s = 0.f;
    for (int i = ty; i < SS; i += 8) {
        float x = Fb[(size_t)i * SS + j];
        float nm = fmaxf(m, x);
        s = s * expf(m - nm) + expf(x - nm);
        m = nm;
    }
    __shared__ float sm[8][32], sv[8][32];
    sm[ty][tx] = m; sv[ty][tx] = s;
    __syncthreads();
    if (ty == 0) {
        float M = sm[0][tx], Sv = sv[0][tx];
#pragma unroll
        for (int q = 1; q < 8; q++) {
            float m2 = sm[q][tx], s2 = sv[q][tx];
            float nm = fmaxf(M, m2);
            Sv = Sv * expf(M - nm) + s2 * expf(m2 - nm);
            M = nm;
        }
        g_colterm[b*SS + j] = M + logf(Sv) - Fb[(size_t)j * SS + j];
    }
}

// ---------------- final scalar ----------------
__global__ void k_final(float* out) {
    __shared__ float red[256];
    int t = threadIdx.x;
    float s = 0.f;
    for (int idx = t; idx < BB*SS; idx += 256) s += g_rowterm[idx] + g_colterm[idx];
    red[t] = s;
    __syncthreads();
    for (int o = 128; o > 0; o >>= 1) {
        if (t < o) red[t] += red[t + o];
        __syncthreads();
    }
    if (t == 0) out[0] = g_gloss + 0.5f * red[0] / (float)(BB*SS);
}

// ---------------- launch ----------------
extern "C" void kernel_launch(void* const* d_in, const int* in_sizes, int n_in,
                              void* d_out, int out_size) {
    const float* img = (const float*)d_in[0];
    const float* txt = (const float*)d_in[1];
    const float* Wv  = (const float*)d_in[2];
    const float* bv  = (const float*)d_in[3];
    const float* Wt  = (const float*)d_in[4];
    const float* bt  = (const float*)d_in[5];
    float* out = (float*)d_out;

    static int attr_done = 0;
    if (!attr_done) {
        cudaFuncSetAttribute(k_patch, cudaFuncAttributeMaxDynamicSharedMemorySize, SMEMSZ);
        cudaFuncSetAttribute(k_tok,   cudaFuncAttributeMaxDynamicSharedMemorySize, SMEMSZ);
        cudaFuncSetAttribute(k_sim,   cudaFuncAttributeMaxDynamicSharedMemorySize, SMEMSZ);
        cudaFuncSetAttribute(k_lgve,  cudaFuncAttributeMaxDynamicSharedMemorySize, SMEMSZ);
        cudaFuncSetAttribute(k_fsim,  cudaFuncAttributeMaxDynamicSharedMemorySize, SMEMSZ);
        attr_done = 1;
    }

    k_init <<<128, 256>>>();                                 // 1
    k_patch<<<dim3(8, 2, BB), 256, SMEMSZ>>>(img, Wv, bv);   // 2 (+colsum)
    k_tok  <<<dim3(4, 2, BB), 256, SMEMSZ>>>(txt, Wt, bt);   // 3 (+colsum, rowss)
    k_gimg <<<dim3(8, BB), 256>>>(Wv, bv);                   // 4
    k_gtxt <<<dim3(8, BB), 256>>>(Wt, bt);                   // 5
    k_sim  <<<dim3(8, 4, BB), 256, SMEMSZ>>>();              // 6  <- ncu target (+minmax)
    k_gnorm<<<128, 32>>>();                                  // 7
    k_gsim <<<64, 256>>>();                                  // 8
    k_gloss<<<1, 64>>>();                                    // 9
    k_lgve <<<dim3(4, 2, BB), 256, SMEMSZ>>>();              // 10 (zdiv + rowss)
    k_fsim <<<dim3(4, 4, BB), 256, SMEMSZ>>>();              // 11 (normalized staging)
    k_frow <<<(BB*SS)/8, 256>>>();
    k_fcol <<<dim3(SS/32, BB), dim3(32, 8)>>>();
    k_final<<<1, 256>>>(out);
}